// round 15
// baseline (speedup 1.0000x reference)
#include <cuda_runtime.h>
#include <cstdint>

#define B_ 64
#define N_ 25
#define C_ 128
#define T_ 256

// ---------------- device scratch ----------------
__device__ float g_z[B_ * N_ * C_ * T_];           // GEMM output per node (pre-mix) [b][n][o][t]
__device__ float g_Bf[3 * 4 * 4 * 2 * 4 * 32 * 4]; // Weff frag order [k][cc][ks][half][wn][lane][4]
__device__ float g_WcT[3 * 128 * 128];             // Wc transposed: [k][i][o]
__device__ float g_sfull[C_], g_s0[C_], g_sT[C_];
__device__ float g_tcs[C_], g_tcb[C_], g_bns[C_], g_bnb[C_], g_bconv[C_];
__device__ float g_rowsum[N_];

__device__ __forceinline__ uint32_t f2tf32(float f) {
    uint32_t r;
    asm("cvt.rna.tf32.f32 %0, %1;" : "=r"(r) : "f"(f));
    return r;
}
__device__ __forceinline__ float tf32f(float f) { return __uint_as_float(f2tf32(f)); }

__device__ __forceinline__ void mma_tf32(float* d, const uint32_t* a, uint32_t b0, uint32_t b1) {
    asm volatile(
        "mma.sync.aligned.m16n8k8.row.col.f32.tf32.tf32.f32 "
        "{%0,%1,%2,%3}, {%4,%5,%6,%7}, {%8,%9}, {%0,%1,%2,%3};"
        : "+f"(d[0]), "+f"(d[1]), "+f"(d[2]), "+f"(d[3])
        : "r"(a[0]), "r"(a[1]), "r"(a[2]), "r"(a[3]), "r"(b0), "r"(b1));
}

// ---------------- precompute stage 1: transpose Wc [o][i][k] -> [k][i][o] ----------------
__global__ void transpose_wc_kernel(const float* __restrict__ Wc)
{
    int idx = blockIdx.x * 256 + threadIdx.x;   // 3*128*128 = 49152
    if (idx < 3 * 128 * 128) {
        int o = idx & 127, i = (idx >> 7) & 127, k = idx >> 14;
        g_WcT[idx] = Wc[(o * 128 + i) * 3 + k];  // write coalesced (o fastest)
    }
}

// ---------------- precompute stage 2: Weff[k][c][o] -> fragment layout g_Bf ----------------
__global__ void precompute_w_kernel(const float* __restrict__ Wg)
{
    int k = blockIdx.x >> 3;
    int c0 = (blockIdx.x & 7) * 16;
    int o = threadIdx.x;  // 128 threads
    __shared__ float wgs[128][17];
    #pragma unroll
    for (int e = 0; e < 16; e++) {
        int idx = o + 128 * e;          // 0..2047
        int i = idx >> 4, j = idx & 15;
        wgs[i][j] = Wg[i * 128 + c0 + j];
    }
    __syncthreads();
    float acc[16];
    #pragma unroll
    for (int j = 0; j < 16; j++) acc[j] = 0.f;
    const float* wt = g_WcT + k * 16384 + o;
    #pragma unroll 4
    for (int i = 0; i < 128; i++) {
        float w = wt[i * 128];
        #pragma unroll
        for (int j = 0; j < 16; j++) acc[j] += w * wgs[i][j];
    }
    int wn = o >> 5, s = o & 31;
    int l2 = s & 7, nt = s >> 3, half = nt >> 1, ntl = nt & 1;
    #pragma unroll
    for (int jj = 0; jj < 16; jj++) {
        int c = c0 + jj;
        int cc = c >> 5, r = c & 31;
        int ks = r >> 3, q = r & 7;
        int lj = q & 3, j = q >> 2;
        int lane = (l2 << 2) | lj;
        int j4 = (ntl << 1) | j;
        size_t idx = ((size_t)(((((k * 4 + cc) * 4 + ks) * 2 + half) * 4 + wn) * 32 + lane) << 2) + j4;
        g_Bf[idx] = __uint_as_float(f2tf32(acc[jj]));
    }
}

// ---------------- precompute stage 3: biases / BN folds / adj row sums ----------------
__global__ void precompute_bias_kernel(
    const float* __restrict__ bg, const float* __restrict__ Wc,
    const float* __restrict__ bc,
    const float* __restrict__ tg, const float* __restrict__ tb,
    const float* __restrict__ tm, const float* __restrict__ tv,
    const float* __restrict__ bng, const float* __restrict__ bnbt,
    const float* __restrict__ bnm, const float* __restrict__ bnv,
    const float* __restrict__ adj)
{
    int o = threadIdx.x;  // 128
    float s0 = 0.f, s1 = 0.f, s2 = 0.f;
    for (int i = 0; i < C_; i++) {
        float b = bg[i];
        const float* w = &Wc[(o * C_ + i) * 3];
        s0 += w[0] * b; s1 += w[1] * b; s2 += w[2] * b;
    }
    g_sfull[o] = s0 + s1 + s2;
    g_s0[o] = s1 + s2;     // t==0: window misses k=0
    g_sT[o] = s0 + s1;     // t==T-1: window misses k=2
    g_bconv[o] = bc[o];
    float ts = tg[o] * rsqrtf(tv[o] + 1e-5f);
    g_tcs[o] = ts; g_tcb[o] = tb[o] - tm[o] * ts;
    float bs = bng[o] * rsqrtf(bnv[o] + 1e-5f);
    g_bns[o] = bs; g_bnb[o] = bnbt[o] - bnm[o] * bs;
    if (o < N_) {
        float r = 0.f;
        for (int n = 0; n < N_; n++) r += adj[o * N_ + n];
        g_rowsum[o] = r;
    }
}

// ---------------- kernel 2: tf32 mma.sync conv-GEMM per (b, n, t-quarter) ----------------
// z[o, t] = sum_{k,c} Weff[k][c][o] * x[c, t+k-1]   (M=64 t, N=128 o, K=384)
// R13 verbatim (measured 262us): one-shot staging, fragment-ordered B.
#define XS_STRIDE 72
#define GEMM_SMEM (128 * XS_STRIDE * 4)   // 36864 B; Ds[64][130] (33280 B) aliases front

__global__ __launch_bounds__(256, 2) void stgemm_kernel(const float* __restrict__ x)
{
    extern __shared__ float smemf[];
    float* xs = smemf;              // [128][72]; col 3 = t0-1, 4..67 = t0..t0+63, 68 = t0+64
    float* Ds = smemf;              // [64][130] (epilogue reuse; [t][o])

    int tid = threadIdx.x, lane = tid & 31, wid = tid >> 5;
    int wm = wid >> 2, wn = wid & 3;
    int t0 = blockIdx.x * 64;
    int node = blockIdx.z * N_ + blockIdx.y;
    const float* xp = x + (size_t)node * C_ * T_;

    float d[2][4][4];
    #pragma unroll
    for (int mt = 0; mt < 2; mt++)
        #pragma unroll
        for (int nt = 0; nt < 4; nt++)
            #pragma unroll
            for (int r = 0; r < 4; r++) d[mt][nt][r] = 0.f;

    // stage x rows [0..128) x t window [t0-1, t0+64], tf32-rounded, in one burst
    #pragma unroll
    for (int e = 0; e < 8; e++) {
        int idx = tid + 256 * e;               // 0..2047
        int ci = idx >> 4, tq = idx & 15;
        float4 v = *(const float4*)&xp[ci * T_ + t0 + 4 * tq];
        v.x = tf32f(v.x); v.y = tf32f(v.y); v.z = tf32f(v.z); v.w = tf32f(v.w);
        *(float4*)&xs[ci * XS_STRIDE + 4 + 4 * tq] = v;
    }
    if (tid < 128) {
        xs[tid * XS_STRIDE + 3] = (t0 > 0) ? tf32f(xp[tid * T_ + t0 - 1]) : 0.f;
    } else {
        int ci = tid - 128;
        xs[ci * XS_STRIDE + 68] = (t0 + 64 < T_) ? tf32f(xp[ci * T_ + t0 + 64]) : 0.f;
    }
    __syncthreads();

    const float* xsb = xs + (lane & 3) * XS_STRIDE + wm * 32 + (lane >> 2) + 3;
    const float4* gB4 = (const float4*)g_Bf;

    #pragma unroll 1
    for (int cc = 0; cc < 4; cc++) {
        const float* xcc = xsb + cc * 32 * XS_STRIDE;
        #pragma unroll 1
        for (int k = 0; k < 3; k++) {
            #pragma unroll
            for (int ks = 0; ks < 4; ks++) {
                int fb = ((k * 4 + cc) * 4 + ks) * 2;
                float4 v0 = gB4[((fb + 0) * 4 + wn) * 32 + lane];
                float4 v1 = gB4[((fb + 1) * 4 + wn) * 32 + lane];
                uint32_t bb[8];
                bb[0] = __float_as_uint(v0.x); bb[1] = __float_as_uint(v0.y);
                bb[2] = __float_as_uint(v0.z); bb[3] = __float_as_uint(v0.w);
                bb[4] = __float_as_uint(v1.x); bb[5] = __float_as_uint(v1.y);
                bb[6] = __float_as_uint(v1.z); bb[7] = __float_as_uint(v1.w);

                const float* xq = xcc + 8 * ks * XS_STRIDE + k;
                #pragma unroll
                for (int mt = 0; mt < 2; mt++) {
                    uint32_t a[4];
                    a[0] = __float_as_uint(xq[mt * 16]);
                    a[1] = __float_as_uint(xq[mt * 16 + 8]);
                    a[2] = __float_as_uint(xq[4 * XS_STRIDE + mt * 16]);
                    a[3] = __float_as_uint(xq[4 * XS_STRIDE + mt * 16 + 8]);
                    #pragma unroll
                    for (int nt = 0; nt < 4; nt++)
                        mma_tf32(d[mt][nt], a, bb[2 * nt], bb[2 * nt + 1]);
                }
            }
        }
    }

    // ---- epilogue: single transpose pass through smem, coalesced store to g_z[o][t] ----
    float* zp = g_z + (size_t)node * C_ * T_;
    __syncthreads();
    #pragma unroll
    for (int mt = 0; mt < 2; mt++) {
        int r = wm * 32 + mt * 16 + (lane >> 2);
        #pragma unroll
        for (int nt = 0; nt < 4; nt++) {
            int cl = wn * 32 + nt * 8 + 2 * (lane & 3);
            *(float2*)&Ds[r * 130 + cl]       = make_float2(d[mt][nt][0], d[mt][nt][1]);
            *(float2*)&Ds[(r + 8) * 130 + cl] = make_float2(d[mt][nt][2], d[mt][nt][3]);
        }
    }
    __syncthreads();
    #pragma unroll
    for (int i = 0; i < 32; i++) {
        int idx = tid + 256 * i;       // 0..8191
        int o = idx >> 6, tt = idx & 63;
        zp[o * T_ + t0 + tt] = Ds[tt * 130 + o];
    }
}

// ---------------- kernel 3: fused node-mix + full epilogue ----------------
// float2 granularity: z-array 50 regs -> ~80 total -> 5-6 CTAs/SM for latency hiding.
__global__ __launch_bounds__(128) void fuse_kernel(const float* __restrict__ x,
                                                   const float* __restrict__ adj,
                                                   float* __restrict__ out)
{
    __shared__ float adjs[N_ * N_];
    int tid = threadIdx.x;
    for (int i = tid; i < N_ * N_; i += 128) adjs[i] = adj[i];
    __syncthreads();

    int b = blockIdx.y;
    int pos = blockIdx.x * 128 + tid;       // float2 index in [0, C*T/2)
    int o = pos >> 7;
    int tbase = 2 * (pos & 127);

    const float2* zb = (const float2*)g_z + (size_t)b * N_ * (C_ * T_ / 2) + pos;
    const float2* xb = (const float2*)x + (size_t)b * N_ * (C_ * T_ / 2) + pos;
    float2* ob_ = (float2*)out + (size_t)b * N_ * (C_ * T_ / 2) + pos;

    // front-load all 25 z float2s: independent LDG.64s, MLP=25
    float2 z[N_];
    #pragma unroll
    for (int n = 0; n < N_; n++) z[n] = zb[n * (C_ * T_ / 2)];

    float sfull = g_sfull[o], s0v = g_s0[o], sTv = g_sT[o], bcv = g_bconv[o];
    float tcs = g_tcs[o], tcb = g_tcb[o], bns = g_bns[o], bnb = g_bnb[o];
    bool e0 = (tbase == 0), eT = (tbase + 1 == T_ - 1);

    float2 r = xb[0];

    #pragma unroll 1
    for (int m = 0; m < N_; m++) {
        float2 res = r;
        if (m + 1 < N_) r = xb[(m + 1) * (C_ * T_ / 2)];

        const float* arow = &adjs[m * N_];
        float2 acc = make_float2(0.f, 0.f);
        #pragma unroll
        for (int n = 0; n < N_; n++) {
            float a = arow[n];
            acc.x += a * z[n].x; acc.y += a * z[n].y;
        }

        float rs = g_rowsum[m];
        float bias_f = bcv + rs * sfull;
        float bias0 = e0 ? (bcv + rs * s0v) : bias_f;
        float bias1 = eT ? (bcv + rs * sTv) : bias_f;

        float p0 = acc.x + bias0;
        float p1 = acc.y + bias1;
        float y0 = fmaxf(tcs * p0 + tcb, 0.f) + res.x;
        float y1 = fmaxf(tcs * p1 + tcb, 0.f) + res.y;
        float2 ov;
        ov.x = fmaxf(bns * y0 + bnb, 0.f);
        ov.y = fmaxf(bns * y1 + bnb, 0.f);
        ob_[m * (C_ * T_ / 2)] = ov;
    }
}

// ---------------- launch ----------------
extern "C" void kernel_launch(void* const* d_in, const int* in_sizes, int n_in,
                              void* d_out, int out_size)
{
    const float* x   = (const float*)d_in[0];
    const float* adj = (const float*)d_in[1];
    const float* Wg  = (const float*)d_in[2];
    const float* bg  = (const float*)d_in[3];
    const float* Wc  = (const float*)d_in[4];
    const float* bc  = (const float*)d_in[5];
    const float* tg  = (const float*)d_in[6];
    const float* tb  = (const float*)d_in[7];
    const float* tm  = (const float*)d_in[8];
    const float* tv  = (const float*)d_in[9];
    const float* bng = (const float*)d_in[10];
    const float* bnb = (const float*)d_in[11];
    const float* bnm = (const float*)d_in[12];
    const float* bnv = (const float*)d_in[13];

    cudaFuncSetAttribute(stgemm_kernel, cudaFuncAttributeMaxDynamicSharedMemorySize, GEMM_SMEM);

    transpose_wc_kernel<<<192, 256>>>(Wc);
    precompute_w_kernel<<<24, 128>>>(Wg);
    precompute_bias_kernel<<<1, 128>>>(bg, Wc, bc, tg, tb, tm, tv, bng, bnb, bnm, bnv, adj);
    stgemm_kernel<<<dim3(4, N_, B_), 256, GEMM_SMEM>>>(x);
    fuse_kernel<<<dim3(C_ * T_ / 2 / 128, B_), 128>>>(x, adj, (float*)d_out);
}

// round 16
// speedup vs baseline: 1.0595x; 1.0595x over previous
#include <cuda_runtime.h>
#include <cuda_fp16.h>
#include <cstdint>

#define B_ 64
#define N_ 25
#define C_ 128
#define T_ 256

// ---------------- device scratch ----------------
__device__ __half g_z[B_ * N_ * C_ * T_];          // GEMM output per node (fp16) [b][n][o][t]
__device__ float g_Bf[3 * 4 * 4 * 2 * 4 * 32 * 4]; // Weff frag order [k][cc][ks][half][wn][lane][4]
__device__ float g_WcT[3 * 128 * 128];             // Wc transposed: [k][i][o]
__device__ float g_sfull[C_], g_s0[C_], g_sT[C_];
__device__ float g_tcs[C_], g_tcb[C_], g_bns[C_], g_bnb[C_], g_bconv[C_];
__device__ float g_rowsum[N_];

__device__ __forceinline__ uint32_t f2tf32(float f) {
    uint32_t r;
    asm("cvt.rna.tf32.f32 %0, %1;" : "=r"(r) : "f"(f));
    return r;
}
__device__ __forceinline__ float tf32f(float f) { return __uint_as_float(f2tf32(f)); }

__device__ __forceinline__ void mma_tf32(float* d, const uint32_t* a, uint32_t b0, uint32_t b1) {
    asm volatile(
        "mma.sync.aligned.m16n8k8.row.col.f32.tf32.tf32.f32 "
        "{%0,%1,%2,%3}, {%4,%5,%6,%7}, {%8,%9}, {%0,%1,%2,%3};"
        : "+f"(d[0]), "+f"(d[1]), "+f"(d[2]), "+f"(d[3])
        : "r"(a[0]), "r"(a[1]), "r"(a[2]), "r"(a[3]), "r"(b0), "r"(b1));
}

// ---------------- precompute stage 1: transpose Wc [o][i][k] -> [k][i][o] ----------------
__global__ void transpose_wc_kernel(const float* __restrict__ Wc)
{
    int idx = blockIdx.x * 256 + threadIdx.x;   // 3*128*128 = 49152
    if (idx < 3 * 128 * 128) {
        int o = idx & 127, i = (idx >> 7) & 127, k = idx >> 14;
        g_WcT[idx] = Wc[(o * 128 + i) * 3 + k];  // write coalesced (o fastest)
    }
}

// ---------------- precompute stage 2: Weff[k][c][o] -> fragment layout g_Bf ----------------
__global__ void precompute_w_kernel(const float* __restrict__ Wg)
{
    int k = blockIdx.x >> 3;
    int c0 = (blockIdx.x & 7) * 16;
    int o = threadIdx.x;  // 128 threads
    __shared__ float wgs[128][17];
    #pragma unroll
    for (int e = 0; e < 16; e++) {
        int idx = o + 128 * e;          // 0..2047
        int i = idx >> 4, j = idx & 15;
        wgs[i][j] = Wg[i * 128 + c0 + j];
    }
    __syncthreads();
    float acc[16];
    #pragma unroll
    for (int j = 0; j < 16; j++) acc[j] = 0.f;
    const float* wt = g_WcT + k * 16384 + o;
    #pragma unroll 4
    for (int i = 0; i < 128; i++) {
        float w = wt[i * 128];
        #pragma unroll
        for (int j = 0; j < 16; j++) acc[j] += w * wgs[i][j];
    }
    int wn = o >> 5, s = o & 31;
    int l2 = s & 7, nt = s >> 3, half = nt >> 1, ntl = nt & 1;
    #pragma unroll
    for (int jj = 0; jj < 16; jj++) {
        int c = c0 + jj;
        int cc = c >> 5, r = c & 31;
        int ks = r >> 3, q = r & 7;
        int lj = q & 3, j = q >> 2;
        int lane = (l2 << 2) | lj;
        int j4 = (ntl << 1) | j;
        size_t idx = ((size_t)(((((k * 4 + cc) * 4 + ks) * 2 + half) * 4 + wn) * 32 + lane) << 2) + j4;
        g_Bf[idx] = __uint_as_float(f2tf32(acc[jj]));
    }
}

// ---------------- precompute stage 3: biases / BN folds / adj row sums ----------------
__global__ void precompute_bias_kernel(
    const float* __restrict__ bg, const float* __restrict__ Wc,
    const float* __restrict__ bc,
    const float* __restrict__ tg, const float* __restrict__ tb,
    const float* __restrict__ tm, const float* __restrict__ tv,
    const float* __restrict__ bng, const float* __restrict__ bnbt,
    const float* __restrict__ bnm, const float* __restrict__ bnv,
    const float* __restrict__ adj)
{
    int o = threadIdx.x;  // 128
    float s0 = 0.f, s1 = 0.f, s2 = 0.f;
    for (int i = 0; i < C_; i++) {
        float b = bg[i];
        const float* w = &Wc[(o * C_ + i) * 3];
        s0 += w[0] * b; s1 += w[1] * b; s2 += w[2] * b;
    }
    g_sfull[o] = s0 + s1 + s2;
    g_s0[o] = s1 + s2;     // t==0: window misses k=0
    g_sT[o] = s0 + s1;     // t==T-1: window misses k=2
    g_bconv[o] = bc[o];
    float ts = tg[o] * rsqrtf(tv[o] + 1e-5f);
    g_tcs[o] = ts; g_tcb[o] = tb[o] - tm[o] * ts;
    float bs = bng[o] * rsqrtf(bnv[o] + 1e-5f);
    g_bns[o] = bs; g_bnb[o] = bnbt[o] - bnm[o] * bs;
    if (o < N_) {
        float r = 0.f;
        for (int n = 0; n < N_; n++) r += adj[o * N_ + n];
        g_rowsum[o] = r;
    }
}

// ---------------- kernel 2: tf32 mma.sync conv-GEMM per (b, n, t-quarter) ----------------
// z[o, t] = sum_{k,c} Weff[k][c][o] * x[c, t+k-1]   (M=64 t, N=128 o, K=384)
// R13 mainloop verbatim; epilogue now packs half2 into fp16 g_z.
#define XS_STRIDE 72
#define GEMM_SMEM (128 * XS_STRIDE * 4)   // 36864 B; Ds[64][130] (33280 B) aliases front

__global__ __launch_bounds__(256, 2) void stgemm_kernel(const float* __restrict__ x)
{
    extern __shared__ float smemf[];
    float* xs = smemf;              // [128][72]; col 3 = t0-1, 4..67 = t0..t0+63, 68 = t0+64
    float* Ds = smemf;              // [64][130] (epilogue reuse; [t][o])

    int tid = threadIdx.x, lane = tid & 31, wid = tid >> 5;
    int wm = wid >> 2, wn = wid & 3;
    int t0 = blockIdx.x * 64;
    int node = blockIdx.z * N_ + blockIdx.y;
    const float* xp = x + (size_t)node * C_ * T_;

    float d[2][4][4];
    #pragma unroll
    for (int mt = 0; mt < 2; mt++)
        #pragma unroll
        for (int nt = 0; nt < 4; nt++)
            #pragma unroll
            for (int r = 0; r < 4; r++) d[mt][nt][r] = 0.f;

    // stage x rows [0..128) x t window [t0-1, t0+64], tf32-rounded, in one burst
    #pragma unroll
    for (int e = 0; e < 8; e++) {
        int idx = tid + 256 * e;               // 0..2047
        int ci = idx >> 4, tq = idx & 15;
        float4 v = *(const float4*)&xp[ci * T_ + t0 + 4 * tq];
        v.x = tf32f(v.x); v.y = tf32f(v.y); v.z = tf32f(v.z); v.w = tf32f(v.w);
        *(float4*)&xs[ci * XS_STRIDE + 4 + 4 * tq] = v;
    }
    if (tid < 128) {
        xs[tid * XS_STRIDE + 3] = (t0 > 0) ? tf32f(xp[tid * T_ + t0 - 1]) : 0.f;
    } else {
        int ci = tid - 128;
        xs[ci * XS_STRIDE + 68] = (t0 + 64 < T_) ? tf32f(xp[ci * T_ + t0 + 64]) : 0.f;
    }
    __syncthreads();

    const float* xsb = xs + (lane & 3) * XS_STRIDE + wm * 32 + (lane >> 2) + 3;
    const float4* gB4 = (const float4*)g_Bf;

    #pragma unroll 1
    for (int cc = 0; cc < 4; cc++) {
        const float* xcc = xsb + cc * 32 * XS_STRIDE;
        #pragma unroll 1
        for (int k = 0; k < 3; k++) {
            #pragma unroll
            for (int ks = 0; ks < 4; ks++) {
                int fb = ((k * 4 + cc) * 4 + ks) * 2;
                float4 v0 = gB4[((fb + 0) * 4 + wn) * 32 + lane];
                float4 v1 = gB4[((fb + 1) * 4 + wn) * 32 + lane];
                uint32_t bb[8];
                bb[0] = __float_as_uint(v0.x); bb[1] = __float_as_uint(v0.y);
                bb[2] = __float_as_uint(v0.z); bb[3] = __float_as_uint(v0.w);
                bb[4] = __float_as_uint(v1.x); bb[5] = __float_as_uint(v1.y);
                bb[6] = __float_as_uint(v1.z); bb[7] = __float_as_uint(v1.w);

                const float* xq = xcc + 8 * ks * XS_STRIDE + k;
                #pragma unroll
                for (int mt = 0; mt < 2; mt++) {
                    uint32_t a[4];
                    a[0] = __float_as_uint(xq[mt * 16]);
                    a[1] = __float_as_uint(xq[mt * 16 + 8]);
                    a[2] = __float_as_uint(xq[4 * XS_STRIDE + mt * 16]);
                    a[3] = __float_as_uint(xq[4 * XS_STRIDE + mt * 16 + 8]);
                    #pragma unroll
                    for (int nt = 0; nt < 4; nt++)
                        mma_tf32(d[mt][nt], a, bb[2 * nt], bb[2 * nt + 1]);
                }
            }
        }
    }

    // ---- epilogue: transpose through smem, pack half2, coalesced store to g_z[o][t] ----
    __half* zp = g_z + (size_t)node * C_ * T_;
    __syncthreads();
    #pragma unroll
    for (int mt = 0; mt < 2; mt++) {
        int r = wm * 32 + mt * 16 + (lane >> 2);
        #pragma unroll
        for (int nt = 0; nt < 4; nt++) {
            int cl = wn * 32 + nt * 8 + 2 * (lane & 3);
            *(float2*)&Ds[r * 130 + cl]       = make_float2(d[mt][nt][0], d[mt][nt][1]);
            *(float2*)&Ds[(r + 8) * 130 + cl] = make_float2(d[mt][nt][2], d[mt][nt][3]);
        }
    }
    __syncthreads();
    #pragma unroll
    for (int i = 0; i < 16; i++) {
        int idx = tid + 256 * i;       // 0..4095
        int o = idx >> 5, tq = idx & 31;
        int tt = 2 * tq;
        __half2 h = __floats2half2_rn(Ds[tt * 130 + o], Ds[(tt + 1) * 130 + o]);
        *(__half2*)&zp[o * T_ + t0 + tt] = h;
    }
}

// ---------------- kernel 3: fused node-mix + full epilogue ----------------
// R13 float4 structure; z loaded as fp16 (LDG.64, MLP=25), converted once to fp32.
__global__ __launch_bounds__(128) void fuse_kernel(const float* __restrict__ x,
                                                   const float* __restrict__ adj,
                                                   float* __restrict__ out)
{
    __shared__ float adjs[N_ * N_];
    int tid = threadIdx.x;
    for (int i = tid; i < N_ * N_; i += 128) adjs[i] = adj[i];
    __syncthreads();

    int b = blockIdx.y;
    int pos = blockIdx.x * 128 + tid;       // float4 index in [0, C*T/4)
    int o = pos >> 6;
    int tbase = 4 * (pos & 63);

    const __half* zh = g_z + (size_t)b * N_ * C_ * T_ + (size_t)pos * 4;
    const float4* xb = (const float4*)x + (size_t)b * N_ * (C_ * T_ / 4) + pos;
    float4* ob_ = (float4*)out + (size_t)b * N_ * (C_ * T_ / 4) + pos;

    // front-load all 25 z values (LDG.64 each, MLP=25), convert to fp32 once
    float4 z[N_];
    #pragma unroll
    for (int n = 0; n < N_; n++) {
        uint2 raw = *(const uint2*)(zh + (size_t)n * (C_ * T_));
        float2 f01 = __half22float2(*(__half2*)&raw.x);
        float2 f23 = __half22float2(*(__half2*)&raw.y);
        z[n] = make_float4(f01.x, f01.y, f23.x, f23.y);
    }

    float sfull = g_sfull[o], s0v = g_s0[o], sTv = g_sT[o], bcv = g_bconv[o];
    float tcs = g_tcs[o], tcb = g_tcb[o], bns = g_bns[o], bnb = g_bnb[o];
    bool e0 = (tbase == 0), eT = (tbase + 3 == T_ - 1);

    float4 r = xb[0];

    #pragma unroll 1
    for (int m = 0; m < N_; m++) {
        float4 res = r;
        if (m + 1 < N_) r = xb[(m + 1) * (C_ * T_ / 4)];

        const float* arow = &adjs[m * N_];
        float4 acc = make_float4(0.f, 0.f, 0.f, 0.f);
        #pragma unroll
        for (int n = 0; n < N_; n++) {
            float a = arow[n];
            acc.x += a * z[n].x; acc.y += a * z[n].y;
            acc.z += a * z[n].z; acc.w += a * z[n].w;
        }

        float rs = g_rowsum[m];
        float bias_f = bcv + rs * sfull;
        float v[4] = { acc.x, acc.y, acc.z, acc.w };
        float bias[4] = { bias_f, bias_f, bias_f, bias_f };
        if (e0) bias[0] = bcv + rs * s0v;
        if (eT) bias[3] = bcv + rs * sTv;
        float resv[4] = { res.x, res.y, res.z, res.w };
        float ov[4];
        #pragma unroll
        for (int j = 0; j < 4; j++) {
            float p = v[j] + bias[j];
            float y1 = fmaxf(tcs * p + tcb, 0.f);
            float y2 = y1 + resv[j];
            ov[j] = fmaxf(bns * y2 + bnb, 0.f);
        }
        ob_[m * (C_ * T_ / 4)] = make_float4(ov[0], ov[1], ov[2], ov[3]);
    }
}

// ---------------- launch ----------------
extern "C" void kernel_launch(void* const* d_in, const int* in_sizes, int n_in,
                              void* d_out, int out_size)
{
    const float* x   = (const float*)d_in[0];
    const float* adj = (const float*)d_in[1];
    const float* Wg  = (const float*)d_in[2];
    const float* bg  = (const float*)d_in[3];
    const float* Wc  = (const float*)d_in[4];
    const float* bc  = (const float*)d_in[5];
    const float* tg  = (const float*)d_in[6];
    const float* tb  = (const float*)d_in[7];
    const float* tm  = (const float*)d_in[8];
    const float* tv  = (const float*)d_in[9];
    const float* bng = (const float*)d_in[10];
    const float* bnb = (const float*)d_in[11];
    const float* bnm = (const float*)d_in[12];
    const float* bnv = (const float*)d_in[13];

    cudaFuncSetAttribute(stgemm_kernel, cudaFuncAttributeMaxDynamicSharedMemorySize, GEMM_SMEM);

    transpose_wc_kernel<<<192, 256>>>(Wc);
    precompute_w_kernel<<<24, 128>>>(Wg);
    precompute_bias_kernel<<<1, 128>>>(bg, Wc, bc, tg, tb, tm, tv, bng, bnb, bnm, bnv, adj);
    stgemm_kernel<<<dim3(4, N_, B_), 256, GEMM_SMEM>>>(x);
    fuse_kernel<<<dim3(C_ * T_ / 4 / 128, B_), 128>>>(x, adj, (float*)d_out);
}